// round 17
// baseline (speedup 1.0000x reference)
#include <cuda_runtime.h>
#include <cstdint>
#include <cstdio>
#include <cub/cub.cuh>
#include <thrust/iterator/counting_iterator.h>
#include <thrust/iterator/transform_iterator.h>

// ---------------- static scratch (no allocations allowed) ----------------
static constexpr int       MAX_F     = 1600000;
static constexpr int       MAX_SLOTS = MAX_F * 6;
static constexpr int       NB        = 1 << 21;   // buckets: (a<<2)|(b>>17)
static constexpr int       CAPB      = 40;        // lambda_max~13 -> P(ovfl)~1e-10
static constexpr long long SLAB      = (long long)NB * CAPB;  // 83.9M slots (671MB)

__device__ __align__(256) unsigned long long g_slab[SLAB];    // fixed per-bucket slabs
__device__ __align__(256) unsigned int       g_cursor[NB + 1];
__device__ __align__(256) unsigned char      g_uniq[NB + 1];
__device__ __align__(256) unsigned int       g_uniqoff[NB + 1];
__device__ __align__(256) unsigned int       g_edgeid[MAX_SLOTS];
__device__ __align__(256) unsigned long long g_tetscan[MAX_F];
__device__ __align__(256) unsigned char      g_tetidx[MAX_F];
__device__ __align__(256) unsigned char      g_temp[16 * 1024 * 1024];  // CUB temp
__device__ int g_is64;

// ---------------- marching-tets tables ----------------
__constant__ int c_tri_table[16][6] = {
    {-1,-1,-1,-1,-1,-1},{1,0,2,-1,-1,-1},{4,0,3,-1,-1,-1},{1,4,2,1,3,4},
    {3,1,5,-1,-1,-1},{2,3,0,2,5,3},{1,4,0,1,5,4},{4,2,5,-1,-1,-1},
    {4,5,2,-1,-1,-1},{4,1,0,4,5,1},{3,2,0,3,5,2},{1,3,5,-1,-1,-1},
    {4,1,2,4,3,1},{3,0,4,-1,-1,-1},{2,0,1,-1,-1,-1},{-1,-1,-1,-1,-1,-1}};
__constant__ int c_num_tri[16] = {0,1,1,2,1,2,2,1,1,2,2,1,2,1,1,0};
__constant__ int c_edges[12]   = {0,1,0,2,0,3,1,2,1,3,2,3};

// ---------------- dtype detection ----------------
__global__ void k_detect(const int* __restrict__ tet32) {
    if (threadIdx.x != 0 || blockIdx.x != 0) return;
    int nz = 0;
    for (int i = 1; i < 256; i += 2) nz += (tet32[i] != 0);
    g_is64 = (nz == 0) ? 1 : 0;
}

__device__ __forceinline__ void load_tet(const void* tet, int t, long long Nv,
                                         long long v[4]) {
    if (g_is64) {
        const longlong2* p = (const longlong2*)tet;
        longlong2 x = p[2 * t], y = p[2 * t + 1];
        v[0] = x.x; v[1] = x.y; v[2] = y.x; v[3] = y.y;
    } else {
        const int4* p = (const int4*)tet;
        int4 x = p[t];
        v[0] = x.x; v[1] = x.y; v[2] = x.z; v[3] = x.w;
    }
#pragma unroll
    for (int i = 0; i < 4; i++) {
        if (v[i] < 0) v[i] = 0;
        if (v[i] >= Nv) v[i] = Nv - 1;
    }
}

// ---------------- cursor init (every call; graph-replay safe) ----------------
__global__ void k_cursorinit() {
    unsigned bkt = blockIdx.x * blockDim.x + threadIdx.x;
    if (bkt < (unsigned)NB) g_cursor[bkt] = bkt * (unsigned)CAPB;
}

// ---------------- single pass: occ byte + scatter keys into slabs ----------
__global__ void k_buildscatter(const void* __restrict__ tet,
                               const float* __restrict__ sdf,
                               long long Nv, int F) {
    int t = blockIdx.x * blockDim.x + threadIdx.x;
    if (t >= F) return;
    long long v[4];
    load_tet(tet, t, Nv, v);
    int occ = (sdf[v[0]] > 0.f ? 1 : 0) | (sdf[v[1]] > 0.f ? 2 : 0) |
              (sdf[v[2]] > 0.f ? 4 : 0) | (sdf[v[3]] > 0.f ? 8 : 0);
    g_tetidx[t] = (unsigned char)occ;
    if (occ == 0 || occ == 15) return;
#pragma unroll
    for (int e = 0; e < 6; e++) {
        int i0 = c_edges[2 * e], i1 = c_edges[2 * e + 1];
        if (((occ >> i0) ^ (occ >> i1)) & 1) {
            unsigned long long a = (unsigned long long)v[i0];
            unsigned long long b = (unsigned long long)v[i1];
            if (a > b) { unsigned long long tmp = a; a = b; b = tmp; }
            unsigned long long pk =
                (a << 43) | (b << 24) | (unsigned long long)(unsigned)(t * 6 + e);
            unsigned bkt = (unsigned)(pk >> 41);
            unsigned pos = atomicAdd(&g_cursor[bkt], 1u);
            if (pos - bkt * (unsigned)CAPB < (unsigned)CAPB)
                g_slab[pos] = pk;
        }
    }
}

// ---------------- thread-per-bucket: count uniques (O(c^2), c tiny) --------
__global__ void k_bucketcnt() {
    unsigned bkt = blockIdx.x * blockDim.x + threadIdx.x;
    if (bkt >= (unsigned)NB) return;
    unsigned base = bkt * (unsigned)CAPB;
    int c = (int)(g_cursor[bkt] - base);
    if (c > CAPB) c = CAPB;
    if (c <= 1) { g_uniq[bkt] = (unsigned char)(c < 0 ? 0 : c); return; }
    unsigned b17[CAPB];
    for (int i = 0; i < c; i++)
        b17[i] = (unsigned)((g_slab[base + i] >> 24) & 0x1FFFFu);
    unsigned nu = 0;
    for (int i = 0; i < c; i++) {
        bool first = true;
        for (int j = 0; j < i; j++) first &= (b17[j] != b17[i]);
        nu += first;
    }
    g_uniq[bkt] = (unsigned char)nu;
}

// ---------------- scan input functors ----------------
struct U8ToU32 {
    const unsigned char* p;
    __host__ __device__ unsigned operator()(int i) const { return (unsigned)p[i]; }
};
struct TetOp {
    const unsigned char* tetidx;
    __host__ __device__ unsigned long long operator()(int i) const {
        const int nt_tab[16] = {0,1,1,2,1,2,2,1,1,2,2,1,2,1,1,0};
        int nt = nt_tab[tetidx[i] & 15];
        return ((unsigned long long)(nt == 1) << 32) | (unsigned)(nt == 2);
    }
};

// ---------------- thread-per-bucket: ids + edgeid scatter + vertex emit ----
__global__ void k_verts(const float* __restrict__ pos,
                        const float* __restrict__ sdf,
                        long long Nv, float* __restrict__ out, size_t outN) {
    unsigned bkt = blockIdx.x * blockDim.x + threadIdx.x;
    if (bkt >= (unsigned)NB) return;
    unsigned base = bkt * (unsigned)CAPB;
    int c = (int)(g_cursor[bkt] - base);
    if (c <= 0) return;
    if (c > CAPB) c = CAPB;
    unsigned idbase = g_uniqoff[bkt];

    long long a = (long long)(bkt >> 2);
    unsigned bh = (bkt & 3u) << 17;

    // proxy: b_low17 << 6 | original idx (CAPB=40 -> 6 bits)
    unsigned p32[CAPB];
    for (int i = 0; i < c; i++)
        p32[i] = ((unsigned)((g_slab[base + i] >> 24) & 0x1FFFFu) << 6) | (unsigned)i;
    for (int i = 1; i < c; i++) {
        unsigned x = p32[i];
        int j = i - 1;
        while (j >= 0 && p32[j] > x) { p32[j + 1] = p32[j]; j--; }
        p32[j + 1] = x;
    }

    float sa = 0.f, pax = 0.f, pay = 0.f, paz = 0.f;
    if (a < Nv) {
        sa = sdf[a];
        pax = pos[3 * a + 0]; pay = pos[3 * a + 1]; paz = pos[3 * a + 2];
    }

    unsigned nu = 0, prevb = 0xFFFFFFFFu;
    for (int j = 0; j < c; j++) {
        unsigned bl = p32[j] >> 6, orig = p32[j] & 0x3Fu;
        bool first = (bl != prevb);
        prevb = bl;
        if (first) nu++;
        unsigned id = idbase + nu - 1;
        unsigned slot = (unsigned)(g_slab[base + orig] & 0xFFFFFFu);
        if (slot < (unsigned)MAX_SLOTS) g_edgeid[slot] = id;
        if (first) {
            long long b = (long long)(bh | bl);
            if (b < Nv && a < Nv) {
                float sb = sdf[b];
                float denom = sa - sb;
                float wa = -sb / denom, wb = sa / denom;
                size_t o = (size_t)3 * id;
                if (o + 2 < outN) {
                    out[o + 0] = pax * wa + pos[3 * b + 0] * wb;
                    out[o + 1] = pay * wa + pos[3 * b + 1] * wb;
                    out[o + 2] = paz * wa + pos[3 * b + 2] * wb;
                }
            }
        }
    }
}

__global__ void k_faces(int F, float* __restrict__ out, size_t outN) {
    int t = blockIdx.x * blockDim.x + threadIdx.x;
    if (t >= F) return;
    int occ = g_tetidx[t];
    int nt = c_num_tri[occ];
    if (nt == 0) return;

    unsigned M = g_uniqoff[NB];                    // total unique crossing edges
    size_t faceBase = (size_t)3 * M;
    unsigned n1tot = (unsigned)(g_tetscan[F - 1] >> 32);

    unsigned long long incl = g_tetscan[t];
    int nent = nt * 3;
    float vals[6];
#pragma unroll
    for (int j = 0; j < 6; j++) {
        if (j >= nent) break;
        int e = c_tri_table[occ][j];
        vals[j] = (float)g_edgeid[t * 6 + e];
    }

    if (nt == 1) {
        unsigned row = (unsigned)(incl >> 32) - 1;
        size_t o = faceBase + (size_t)3 * row;
        if (o + 2 >= outN) return;
        out[o + 0] = vals[0]; out[o + 1] = vals[1]; out[o + 2] = vals[2];
    } else {
        unsigned r2 = (unsigned)(incl & 0xffffffffu) - 1;
        size_t o = faceBase + (size_t)3 * ((size_t)n1tot + 2 * (size_t)r2);
        if (o + 5 >= outN) return;
#pragma unroll
        for (int j = 0; j < 6; j++) out[o + j] = vals[j];
    }
}

// ---------------- host launcher ----------------
extern "C" void kernel_launch(void* const* d_in, const int* in_sizes, int n_in,
                              void* d_out, int out_size) {
    const float* pos = (const float*)d_in[0];
    const float* sdf = (const float*)d_in[1];
    const void*  tet = d_in[2];

    long long NvLL = in_sizes[1];
    int F  = in_sizes[2] / 4;
    size_t outN = (size_t)out_size;

    unsigned long long* p_tetscan = nullptr;
    unsigned int *p_uniqoff = nullptr;
    unsigned char *p_temp = nullptr, *p_tetidx = nullptr, *p_uniq = nullptr;
    cudaGetSymbolAddress((void**)&p_tetscan, g_tetscan);
    cudaGetSymbolAddress((void**)&p_tetidx,  g_tetidx);
    cudaGetSymbolAddress((void**)&p_uniq,    g_uniq);
    cudaGetSymbolAddress((void**)&p_uniqoff, g_uniqoff);
    cudaGetSymbolAddress((void**)&p_temp,    g_temp);

    const int TB = 256;

    k_detect<<<1, 32>>>((const int*)tet);
    k_cursorinit<<<(NB + TB - 1) / TB, TB>>>();
    k_buildscatter<<<(F + TB - 1) / TB, TB>>>(tet, sdf, NvLL, F);
    k_bucketcnt<<<(NB + TB - 1) / TB, TB>>>();

    // unique-edge id bases: exclusive sum of uniq (u8 -> u32); uniqoff[NB] = M
    size_t tb = 0;
    {
        U8ToU32 op{p_uniq};
        thrust::transform_iterator<U8ToU32, thrust::counting_iterator<int>, unsigned>
            it(thrust::counting_iterator<int>(0), op);
        cub::DeviceScan::ExclusiveSum(nullptr, tb, it, p_uniqoff, NB + 1, 0);
        if (tb > sizeof(g_temp)) tb = sizeof(g_temp);
        cub::DeviceScan::ExclusiveSum(p_temp, tb, it, p_uniqoff, NB + 1, 0);
    }

    float* out = (float*)d_out;
    k_verts<<<(NB + TB - 1) / TB, TB>>>(pos, sdf, NvLL, out, outN);

    // tet-count packing + inclusive scan
    {
        TetOp op{p_tetidx};
        thrust::transform_iterator<TetOp, thrust::counting_iterator<int>, unsigned long long>
            it(thrust::counting_iterator<int>(0), op);
        tb = 0;
        cub::DeviceScan::InclusiveSum(nullptr, tb, it, p_tetscan, F, 0);
        if (tb > sizeof(g_temp)) tb = sizeof(g_temp);
        cub::DeviceScan::InclusiveSum(p_temp, tb, it, p_tetscan, F, 0);
    }

    k_faces<<<(F + TB - 1) / TB, TB>>>(F, out, outN);
}